// round 11
// baseline (speedup 1.0000x reference)
#include <cuda_runtime.h>
#include <cuda_bf16.h>
#include <cstdint>

#define NUM_CLASSES 601
#define OUT_DIM 27
#define PAD_DIM 32          // pad table rows to 32 floats = 128 B = one L1 line
#define CHUNK 32            // rows per warp
#define WARPS_PER_CTA 8
#define CHUNK_BYTES (CHUNK * OUT_DIM * 4)   // 3456 B, 16B-aligned

// Precomputed softmax table: 601 rows x 32 floats (cols 27..31 = 0 padding).
__device__ __align__(128) float g_table[NUM_CLASSES * PAD_DIM];

// ---------------------------------------------------------------------------
// Kernel A: build softmax table. One warp per class row.
// Matches reference exactly: probs = exp(logits) / sum(exp(logits)).
// ---------------------------------------------------------------------------
__global__ void softmax_table_kernel(const float* __restrict__ W) {
    int r = blockIdx.x;
    int c = threadIdx.x;
    float e = 0.0f;
    if (c < OUT_DIM) {
        e = expf(W[r * OUT_DIM + c]);
    }
    float s = e;
    #pragma unroll
    for (int off = 16; off > 0; off >>= 1)
        s += __shfl_xor_sync(0xffffffffu, s, off);
    g_table[r * PAD_DIM + c] = (c < OUT_DIM) ? (e / s) : 0.0f;
}

__device__ __forceinline__ uint32_t smem_u32(const void* p) {
    uint32_t a;
    asm("{ .reg .u64 t; cvta.to.shared.u64 t, %1; cvt.u32.u64 %0, t; }"
        : "=r"(a) : "l"(p));
    return a;
}

// ---------------------------------------------------------------------------
// Kernel B: warp-cooperative gather + TMA bulk store.
// Per warp (one 32-row chunk, R7 structure — huge grid hides latency):
//   - 1 coalesced LDG for the 32 indices
//   - per row: shfl-broadcast index, all lanes read ONE 128B table line
//     (1 L1 wavefront), lanes 0..26 pack the row into SMEM staging
//     (banks 27j+c all distinct -> conflict-free STS)
//   - one cp.async.bulk (3456 B) streams the chunk SMEM->GMEM via the TMA
//     engine, bypassing the L1 store datapath entirely.
// ---------------------------------------------------------------------------
__global__ void __launch_bounds__(256) gather_tma_kernel(
    const int* __restrict__ idx, float* __restrict__ out, int batch)
{
    __shared__ __align__(128) float stage[WARPS_PER_CTA][CHUNK * OUT_DIM];

    const int lane = threadIdx.x & 31;
    const int warp = threadIdx.x >> 5;
    const long long base = ((long long)blockIdx.x * WARPS_PER_CTA + warp) * CHUNK;
    if (base >= batch) return;

    const long long nrows = batch - base;

    if (nrows >= CHUNK) {
        int mi = __ldg(idx + base + lane);
        float* s = stage[warp];

        #pragma unroll
        for (int j = 0; j < CHUNK; j++) {
            int rj = __shfl_sync(0xffffffffu, mi, j);
            float v = g_table[rj * PAD_DIM + lane];
            if (lane < OUT_DIM) s[j * OUT_DIM + lane] = v;
        }
        __syncwarp();
        asm volatile("fence.proxy.async.shared::cta;" ::: "memory");

        if (lane == 0) {
            float* gdst = out + base * OUT_DIM;        // byte offset 3456*k: 16B-aligned
            uint32_t saddr = smem_u32(s);
            asm volatile(
                "cp.async.bulk.global.shared::cta.bulk_group [%0], [%1], %2;"
                :: "l"(gdst), "r"(saddr), "r"((int)CHUNK_BYTES) : "memory");
            asm volatile("cp.async.bulk.commit_group;" ::: "memory");
            asm volatile("cp.async.bulk.wait_group 0;" ::: "memory");
        }
    } else {
        // tail chunk (batch not multiple of CHUNK): direct stores
        int mi = 0;
        if (base + lane < batch) mi = __ldg(idx + base + lane);
        float* orow = out + base * OUT_DIM + lane;
        int n = (int)nrows;
        for (int j = 0; j < n; j++) {
            int rj = __shfl_sync(0xffffffffu, mi, j);
            float v = g_table[rj * PAD_DIM + lane];
            if (lane < OUT_DIM) orow[j * OUT_DIM] = v;
        }
    }
}

extern "C" void kernel_launch(void* const* d_in, const int* in_sizes, int n_in,
                              void* d_out, int out_size) {
    const int* idx;
    const float* W;
    int batch;
    if (in_sizes[0] == NUM_CLASSES * OUT_DIM) {
        W = (const float*)d_in[0];
        idx = (const int*)d_in[1];
        batch = in_sizes[1];
    } else {
        idx = (const int*)d_in[0];
        W = (const float*)d_in[1];
        batch = in_sizes[0];
    }

    softmax_table_kernel<<<NUM_CLASSES, 32>>>(W);

    // 8 warps/block, 32 rows/warp -> 256 rows per block
    long long nblocks = ((long long)batch + (WARPS_PER_CTA * CHUNK - 1)) / (WARPS_PER_CTA * CHUNK);
    gather_tma_kernel<<<(int)nblocks, 256>>>(idx, (float*)d_out, batch);
}